// round 15
// baseline (speedup 1.0000x reference)
#include <cuda_runtime.h>
#include <cuda_fp16.h>
#include <cstdint>

#define BATCH   2
#define SEQ     2048
#define HIDDEN  1024
#define NHEADS  16
#define HDIM    64
#define MTOT    (BATCH*SEQ)
#define NQKV    1152    // 1024 Q + 64 K + 64 V

// ---------------- fp16 scratch ----------------
__device__ __align__(16) __half g_Xh  [MTOT * HIDDEN];
__device__ __align__(16) __half g_Qh  [MTOT * HIDDEN];   // pre-scaled by log2e/8
__device__ __align__(16) __half g_Kh  [MTOT * HDIM];
__device__ __align__(16) __half g_Vh  [MTOT * HDIM];
__device__ __align__(16) __half g_Ah  [MTOT * HIDDEN];
__device__ __align__(16) __half g_Wqkv[HIDDEN * NQKV];
__device__ __align__(16) __half g_Woh [HIDDEN * HIDDEN];
__device__ __align__(16) float  g_bqkv[NQKV];

// ---------------- helpers ----------------
__device__ __forceinline__ uint32_t smem_u32(const void* p) {
    uint32_t a;
    asm("{ .reg .u64 t; cvta.to.shared.u64 t, %1; cvt.u32.u64 %0, t; }" : "=r"(a) : "l"(p));
    return a;
}
__device__ __forceinline__ void mma16(float* c, const uint32_t* a, const uint32_t* b) {
    asm volatile(
        "mma.sync.aligned.m16n8k16.row.col.f32.f16.f16.f32 "
        "{%0,%1,%2,%3},{%4,%5,%6,%7},{%8,%9},{%0,%1,%2,%3};"
        : "+f"(c[0]), "+f"(c[1]), "+f"(c[2]), "+f"(c[3])
        : "r"(a[0]), "r"(a[1]), "r"(a[2]), "r"(a[3]), "r"(b[0]), "r"(b[1]));
}
__device__ __forceinline__ void ldm_x4(uint32_t* r, uint32_t a) {
    asm volatile("ldmatrix.sync.aligned.m8n8.x4.shared.b16 {%0,%1,%2,%3}, [%4];"
        : "=r"(r[0]), "=r"(r[1]), "=r"(r[2]), "=r"(r[3]) : "r"(a));
}
__device__ __forceinline__ void ldm_x4t(uint32_t* r, uint32_t a) {
    asm volatile("ldmatrix.sync.aligned.m8n8.x4.trans.shared.b16 {%0,%1,%2,%3}, [%4];"
        : "=r"(r[0]), "=r"(r[1]), "=r"(r[2]), "=r"(r[3]) : "r"(a));
}
__device__ __forceinline__ uint32_t packh2(float a, float b) {
    __half2 h = __floats2half2_rn(a, b);
    return *(uint32_t*)&h;
}
#define CP_A16(dst, src) \
    asm volatile("cp.async.cg.shared.global [%0], [%1], 16;" :: "r"(dst), "l"(src) : "memory")
#define CP_COMMIT() asm volatile("cp.async.commit_group;" ::: "memory")
#define CP_WAIT(n)  asm volatile("cp.async.wait_group %0;" :: "n"(n) : "memory")

// ============ convert: fp32 inputs -> fp16 scratch ===========================
__global__ __launch_bounds__(256)
void conv_kernel(const float* __restrict__ X,
                 const float* __restrict__ Wq, const float* __restrict__ bq,
                 const float* __restrict__ Wk, const float* __restrict__ bk,
                 const float* __restrict__ Wv, const float* __restrict__ bv,
                 const float* __restrict__ Wo)
{
    int idx = blockIdx.x * 256 + threadIdx.x;
    if (idx < 1048576) {
        float4 v = ((const float4*)X)[idx];
        *(__half2*)&g_Xh[idx * 4]     = __floats2half2_rn(v.x, v.y);
        *(__half2*)&g_Xh[idx * 4 + 2] = __floats2half2_rn(v.z, v.w);
    } else if (idx < 1310720) {
        int i = idx - 1048576;
        float4 v = ((const float4*)Wo)[i];
        *(__half2*)&g_Woh[i * 4]     = __floats2half2_rn(v.x, v.y);
        *(__half2*)&g_Woh[i * 4 + 2] = __floats2half2_rn(v.z, v.w);
    } else if (idx < 1605632) {
        int u = idx - 1310720;
        int row = u / 288, c = (u % 288) * 4;
        float4 v;
        if (c < 1024)      v = *(const float4*)(Wq + row * 1024 + c);
        else if (c < 1088) v = *(const float4*)(Wk + row * 64 + c - 1024);
        else               v = *(const float4*)(Wv + row * 64 + c - 1088);
        __half* d = &g_Wqkv[row * NQKV + c];
        *(__half2*)d       = __floats2half2_rn(v.x, v.y);
        *(__half2*)(d + 2) = __floats2half2_rn(v.z, v.w);
    } else if (idx < 1605920) {
        int c = (idx - 1605632) * 4;
        float4 v;
        if (c < 1024)      v = *(const float4*)(bq + c);
        else if (c < 1088) v = *(const float4*)(bk + c - 1024);
        else               v = *(const float4*)(bv + c - 1088);
        *(float4*)&g_bqkv[c] = v;
    }
}

// ============ GEMM fp16: 128x128 tile, K-chunk 64, 3-stage cp.async ==========
#define GSTA 18432            // 128*72*2 (A part of a stage)
#define GSTW 17408            // 64*136*2 (W part of a stage)
#define GSTAGE 35840
#define GBI_B 107520          // 3*GSTAGE
#define G_SMEM 108032

__device__ __forceinline__ void g_issue(uint32_t sb, int buf, int k0, int tid,
                                        const __half* A, const __half* W,
                                        int WN, int m0, int n0)
{
    const uint32_t as = sb + buf * GSTAGE;
    const uint32_t ws = as + GSTA;
#pragma unroll
    for (int l = 0; l < 4; l++) {
        int idx = tid + l * 256;
        int r = idx >> 3, c8 = idx & 7;
        CP_A16(as + (uint32_t)(r * 72 + c8 * 8) * 2,
               (const void*)(A + (size_t)(m0 + r) * HIDDEN + k0 + c8 * 8));
    }
#pragma unroll
    for (int l = 0; l < 4; l++) {
        int idx = tid + l * 256;
        int r = idx >> 4, c8 = idx & 15;
        CP_A16(ws + (uint32_t)(r * 136 + c8 * 8) * 2,
               (const void*)(W + (size_t)(k0 + r) * WN + n0 + c8 * 8));
    }
}

__global__ __launch_bounds__(256, 2)
void gemm_h(const __half* __restrict__ A, const __half* __restrict__ W, int WN,
            const float* __restrict__ bias, float* __restrict__ C, int mode)
{
    extern __shared__ char smc[];
    const uint32_t sb = smem_u32(smc);
    float* Bias = (float*)(smc + GBI_B);

    const int tid = threadIdx.x, lane = tid & 31, wid = tid >> 5;
    const int g = lane >> 2, k4 = lane & 3;
    const int wr = wid >> 2, wc = wid & 3;
    const int m0 = blockIdx.y * 128;
    const int n0 = blockIdx.x * 128;

    if (tid < 128) Bias[tid] = bias[n0 + tid];

    g_issue(sb, 0, 0,  tid, A, W, WN, m0, n0); CP_COMMIT();
    g_issue(sb, 1, 64, tid, A, W, WN, m0, n0); CP_COMMIT();

    float acc[4][4][4] = {};
    int buf = 0;

    for (int kc = 0; kc < 16; ++kc) {
        if (kc < 15) CP_WAIT(1);
        else         CP_WAIT(0);
        __syncthreads();

        if (kc < 14) {
            int nb = buf + 2; if (nb >= 3) nb -= 3;
            g_issue(sb, nb, (kc + 2) * 64, tid, A, W, WN, m0, n0);
            CP_COMMIT();
        }

        const uint32_t as = sb + buf * GSTAGE;
        const uint32_t ws = as + GSTA;
        const int i = lane >> 3;
#pragma unroll
        for (int ks = 0; ks < 4; ++ks) {
            uint32_t a[4][4];
#pragma unroll
            for (int mt = 0; mt < 4; mt++)
                ldm_x4(a[mt], as + (uint32_t)((wr * 64 + mt * 16 + (lane & 15)) * 72
                                              + ks * 16 + (lane >> 4) * 8) * 2);
#pragma unroll
            for (int p = 0; p < 2; p++) {
                uint32_t b4[4];
                ldm_x4t(b4, ws + (uint32_t)((ks * 16 + (i & 1) * 8 + (lane & 7)) * 136
                                            + wc * 32 + p * 16 + (i >> 1) * 8) * 2);
#pragma unroll
                for (int mt = 0; mt < 4; mt++) {
                    mma16(acc[mt][2 * p],     a[mt], b4);
                    mma16(acc[mt][2 * p + 1], a[mt], b4 + 2);
                }
            }
        }
        if (++buf == 3) buf = 0;
    }

    // ---- epilogue: Q scaled by log2e/8 so softmax can use ex2 directly ----
    const float sc = (mode == 0 && n0 < 1024) ? 0.18033688f : 1.0f;
#pragma unroll
    for (int mt = 0; mt < 4; mt++) {
        const int r = m0 + wr * 64 + mt * 16 + g;
#pragma unroll
        for (int nt = 0; nt < 4; nt++) {
            const int c = wc * 32 + nt * 8 + 2 * k4;
            float v00 = (acc[mt][nt][0] + Bias[c])     * sc;
            float v01 = (acc[mt][nt][1] + Bias[c + 1]) * sc;
            float v10 = (acc[mt][nt][2] + Bias[c])     * sc;
            float v11 = (acc[mt][nt][3] + Bias[c + 1]) * sc;
            if (mode == 1) {
                float2 a0 = { v00, v01 }, a1 = { v10, v11 };
                *(float2*)(C + (size_t)r * HIDDEN + n0 + c) = a0;
                *(float2*)(C + (size_t)(r + 8) * HIDDEN + n0 + c) = a1;
            } else if (n0 < 1024) {
                *(__half2*)&g_Qh[(size_t)r * HIDDEN + n0 + c]       = __floats2half2_rn(v00, v01);
                *(__half2*)&g_Qh[(size_t)(r + 8) * HIDDEN + n0 + c] = __floats2half2_rn(v10, v11);
            } else if (c < 64) {
                *(__half2*)&g_Kh[(size_t)r * HDIM + c]       = __floats2half2_rn(v00, v01);
                *(__half2*)&g_Kh[(size_t)(r + 8) * HDIM + c] = __floats2half2_rn(v10, v11);
            } else {
                *(__half2*)&g_Vh[(size_t)r * HDIM + c - 64]       = __floats2half2_rn(v00, v01);
                *(__half2*)&g_Vh[(size_t)(r + 8) * HDIM + c - 64] = __floats2half2_rn(v10, v11);
            }
        }
    }
}

// ============ attention: 64 rows x 2 heads/CTA, 256 thr, occ 2 ===============
// Two independent barrier domains per SM (occ 2) + MQA K/V sharing (2 heads).
// Warps 0-3 -> head h0 (rows w*16), warps 4-7 -> head h1.
#define AQ_B  0               // 2 heads x 9216 (64 rows x 72 halves)
#define AKV_B 18432           // K/V double buffer: buf*36864, V at +18432
#define AM_B  92160           // mask halves: 2 x 128 x 2B
#define ATT_SMEM 92672

__global__ __launch_bounds__(256, 2)
void attn_h(const int* __restrict__ mask)
{
    extern __shared__ char smc[];
    const uint32_t sb = smem_u32(smc);

    const int tid = threadIdx.x, lane = tid & 31, wid = tid >> 5;
    const int g = lane >> 2, k4 = lane & 3;
    const int ln = lane & 15;
    const int hsel = wid >> 2;          // 0..1: which head this warp serves
    const int wrow = wid & 3;           // row-tile within the head (rows wrow*16..)
    const int qt = blockIdx.x, hp = blockIdx.y, b = blockIdx.z;
    const int h = hp * 2 + hsel;

    const __half* Kb = g_Kh + (size_t)b * SEQ * HDIM;
    const __half* Vb = g_Vh + (size_t)b * SEQ * HDIM;
    const int*    Mb = mask + (size_t)b * SEQ;
    unsigned short* MskH = (unsigned short*)(smc + AM_B);

    // ---- prologue: Q tiles (both heads, 64 rows each) + K/V tile 0 ----
#pragma unroll
    for (int l = 0; l < 4; l++) {
        int idx = tid + l * 256;            // 0..1023
        int hh = idx >> 9;                  // 0..1
        int r  = (idx >> 3) & 63;
        int c8 = idx & 7;
        const __half* src = g_Qh + ((size_t)(b * SEQ + qt * 64 + r)) * HIDDEN
                          + (hp * 2 + hh) * HDIM + c8 * 8;
        CP_A16(sb + AQ_B + hh * 9216 + (uint32_t)(r * 72 + c8 * 8) * 2, (const void*)src);
    }
    {
        const uint32_t kb = sb + AKV_B;
#pragma unroll
        for (int l = 0; l < 8; l++) {
            int idx = tid + l * 256;        // 0..2047
            int kv = idx >> 10;             // 0 = K, 1 = V
            int r  = (idx >> 3) & 127;
            int c8 = idx & 7;
            const __half* src = (kv ? Vb : Kb) + (size_t)r * HDIM + c8 * 8;
            CP_A16(kb + kv * 18432 + (uint32_t)(r * 72 + c8 * 8) * 2, (const void*)src);
        }
        if (tid < 128) MskH[tid] = Mb[tid] ? 0x3C00 : 0;
        CP_COMMIT();
    }
    CP_WAIT(0);
    __syncthreads();

    uint32_t qa[4][4];
#pragma unroll
    for (int ks = 0; ks < 4; ks++)
        ldm_x4(qa[ks], sb + AQ_B + hsel * 9216
                        + (uint32_t)((wrow * 16 + ln) * 72 + ks * 16 + (lane >> 4) * 8) * 2);

    float oacc[8][4] = {};
    float sum0 = 0.f, sum1 = 0.f;

    for (int kt = 0; kt < 16; ++kt) {
        if (kt > 0) {
            CP_WAIT(0);
            __syncthreads();
        }
        if (kt < 15) {
            const uint32_t kb = sb + AKV_B + ((kt + 1) & 1) * 36864;
            const size_t base = (size_t)((kt + 1) * 128) * HDIM;
#pragma unroll
            for (int l = 0; l < 8; l++) {
                int idx = tid + l * 256;
                int kv = idx >> 10;
                int r  = (idx >> 3) & 127;
                int c8 = idx & 7;
                const __half* src = (kv ? Vb : Kb) + base + (size_t)r * HDIM + c8 * 8;
                CP_A16(kb + kv * 18432 + (uint32_t)(r * 72 + c8 * 8) * 2, (const void*)src);
            }
            if (tid < 128) MskH[((kt + 1) & 1) * 128 + tid] = Mb[(kt + 1) * 128 + tid] ? 0x3C00 : 0;
            CP_COMMIT();
        }

        const uint32_t ksh = sb + AKV_B + (kt & 1) * 36864;
        const uint32_t vsh = ksh + 18432;
        const unsigned short* Mw = MskH + (kt & 1) * 128;

#pragma unroll
        for (int hf = 0; hf < 2; ++hf) {
            // ---- S' = (Q*log2e/8) @ K^T over 64 keys, fp32 accumulators ----
            float sacc[8][4] = {};
#pragma unroll
            for (int nt = 0; nt < 8; nt++) {
                const int krow = hf * 64 + nt * 8 + (lane & 7);
#pragma unroll
                for (int ks2 = 0; ks2 < 2; ks2++) {
                    uint32_t kb4[4];
                    ldm_x4(kb4, ksh + (uint32_t)(krow * 72 + ks2 * 32 + (lane >> 3) * 8) * 2);
                    mma16(sacc[nt], qa[2 * ks2],     kb4);
                    mma16(sacc[nt], qa[2 * ks2 + 1], kb4 + 2);
                }
            }
            // ---- P = 2^(S') via ex2.f16x2, masked; rowsum via add.f16x2 ----
            uint32_t ph0[8], ph1[8];
            uint32_t hs0 = 0, hs1 = 0;      // packed f16x2 partial row sums
#pragma unroll
            for (int nt = 0; nt < 8; nt++) {
                const int c = hf * 64 + nt * 8 + 2 * k4;
                uint32_t e01 = packh2(sacc[nt][0], sacc[nt][1]);
                uint32_t e23 = packh2(sacc[nt][2], sacc[nt][3]);
                asm("ex2.approx.f16x2 %0, %1;" : "=r"(e01) : "r"(e01));
                asm("ex2.approx.f16x2 %0, %1;" : "=r"(e23) : "r"(e23));
                const uint32_t mh = *(const uint32_t*)&Mw[c];
                asm("mul.rn.f16x2 %0, %1, %2;" : "=r"(ph0[nt]) : "r"(e01), "r"(mh));
                asm("mul.rn.f16x2 %0, %1, %2;" : "=r"(ph1[nt]) : "r"(e23), "r"(mh));
                asm("add.rn.f16x2 %0, %0, %1;" : "+r"(hs0) : "r"(ph0[nt]));
                asm("add.rn.f16x2 %0, %0, %1;" : "+r"(hs1) : "r"(ph1[nt]));
            }
            // promote 64-key partial sums to fp32
            {
                __half2 h0 = *(__half2*)&hs0, h1 = *(__half2*)&hs1;
                float2 f0 = __half22float2(h0), f1 = __half22float2(h1);
                sum0 += f0.x + f0.y;
                sum1 += f1.x + f1.y;
            }
            // ---- O += P @ V (fp32 acc) ----
#pragma unroll
            for (int j = 0; j < 4; j++) {
                uint32_t a[4] = { ph0[2 * j], ph1[2 * j], ph0[2 * j + 1], ph1[2 * j + 1] };
                const int vrow = hf * 64 + j * 16 + ln;
#pragma unroll
                for (int d2 = 0; d2 < 4; d2++) {
                    uint32_t vb4[4];
                    ldm_x4t(vb4, vsh + (uint32_t)(vrow * 72 + d2 * 16 + (lane >> 4) * 8) * 2);
                    mma16(oacc[2 * d2],     a, vb4);
                    mma16(oacc[2 * d2 + 1], a, vb4 + 2);
                }
            }
        }
    }

    // ---- quad reduction across k4 lanes ----
    sum0 += __shfl_xor_sync(0xffffffffu, sum0, 1);
    sum0 += __shfl_xor_sync(0xffffffffu, sum0, 2);
    sum1 += __shfl_xor_sync(0xffffffffu, sum1, 1);
    sum1 += __shfl_xor_sync(0xffffffffu, sum1, 2);
    const float inv0 = 1.f / sum0;
    const float inv1 = 1.f / sum1;

    __half* Ob = g_Ah + ((size_t)(b * SEQ + qt * 64 + wrow * 16 + g)) * HIDDEN + h * HDIM;
#pragma unroll
    for (int d = 0; d < 8; d++) {
        int c = d * 8 + 2 * k4;
        *(__half2*)(Ob + c) = __floats2half2_rn(oacc[d][0] * inv0, oacc[d][1] * inv0);
        *(__half2*)(Ob + (size_t)8 * HIDDEN + c) = __floats2half2_rn(oacc[d][2] * inv1,
                                                                     oacc[d][3] * inv1);
    }
}

// ---------------- launch --------------------------------------------------
extern "C" void kernel_launch(void* const* d_in, const int* in_sizes, int n_in,
                              void* d_out, int out_size)
{
    const float* X    = (const float*)d_in[0];
    const float* Wq   = (const float*)d_in[1];
    const float* bq   = (const float*)d_in[2];
    const float* Wk   = (const float*)d_in[3];
    const float* bk   = (const float*)d_in[4];
    const float* Wv   = (const float*)d_in[5];
    const float* bv   = (const float*)d_in[6];
    const float* Wo   = (const float*)d_in[7];
    const float* bo   = (const float*)d_in[8];
    const int*   mask = (const int*)d_in[9];
    float* out = (float*)d_out;

    __half *xh, *ah, *wqkv, *woh;
    float* bqkv;
    cudaGetSymbolAddress((void**)&xh,   g_Xh);
    cudaGetSymbolAddress((void**)&ah,   g_Ah);
    cudaGetSymbolAddress((void**)&wqkv, g_Wqkv);
    cudaGetSymbolAddress((void**)&woh,  g_Woh);
    cudaGetSymbolAddress((void**)&bqkv, g_bqkv);

    cudaFuncSetAttribute(gemm_h, cudaFuncAttributeMaxDynamicSharedMemorySize, G_SMEM);
    cudaFuncSetAttribute(attn_h, cudaFuncAttributeMaxDynamicSharedMemorySize, ATT_SMEM);

    // 0) convert inputs to fp16 scratch
    conv_kernel<<<6274, 256>>>(X, Wq, bq, Wk, bk, Wv, bv, Wo);

    // 1) fused QKV projection
    dim3 g1(NQKV / 128, MTOT / 128);
    gemm_h<<<g1, 256, G_SMEM>>>(xh, wqkv, NQKV, bqkv, nullptr, 0);

    // 2) attention: 64 rows x 2 heads per CTA, occ 2
    dim3 g2(SEQ / 64, NHEADS / 2, BATCH);
    attn_h<<<g2, 256, ATT_SMEM>>>(mask);

    // 3) O projection -> d_out (f32 + bias)
    dim3 g3(HIDDEN / 128, MTOT / 128);
    gemm_h<<<g3, 256, G_SMEM>>>(ah, woh, HIDDEN, bo, out, 1);
}

// round 16
// speedup vs baseline: 1.0441x; 1.0441x over previous
#include <cuda_runtime.h>
#include <cuda_fp16.h>
#include <cstdint>

#define BATCH   2
#define SEQ     2048
#define HIDDEN  1024
#define NHEADS  16
#define HDIM    64
#define MTOT    (BATCH*SEQ)
#define NQKV    1152    // 1024 Q + 64 K + 64 V

// ---------------- fp16 scratch ----------------
__device__ __align__(16) __half g_Xh  [MTOT * HIDDEN];
__device__ __align__(16) __half g_Qh  [MTOT * HIDDEN];   // pre-scaled by log2e/8
__device__ __align__(16) __half g_Kh  [MTOT * HDIM];
__device__ __align__(16) __half g_Vh  [MTOT * HDIM];
__device__ __align__(16) __half g_Ah  [MTOT * HIDDEN];
__device__ __align__(16) __half g_Wqkv[HIDDEN * NQKV];
__device__ __align__(16) __half g_Woh [HIDDEN * HIDDEN];
__device__ __align__(16) float  g_bqkv[NQKV];

// ---------------- helpers ----------------
__device__ __forceinline__ uint32_t smem_u32(const void* p) {
    uint32_t a;
    asm("{ .reg .u64 t; cvta.to.shared.u64 t, %1; cvt.u32.u64 %0, t; }" : "=r"(a) : "l"(p));
    return a;
}
__device__ __forceinline__ void mma16(float* c, const uint32_t* a, const uint32_t* b) {
    asm volatile(
        "mma.sync.aligned.m16n8k16.row.col.f32.f16.f16.f32 "
        "{%0,%1,%2,%3},{%4,%5,%6,%7},{%8,%9},{%0,%1,%2,%3};"
        : "+f"(c[0]), "+f"(c[1]), "+f"(c[2]), "+f"(c[3])
        : "r"(a[0]), "r"(a[1]), "r"(a[2]), "r"(a[3]), "r"(b[0]), "r"(b[1]));
}
__device__ __forceinline__ void ldm_x4(uint32_t* r, uint32_t a) {
    asm volatile("ldmatrix.sync.aligned.m8n8.x4.shared.b16 {%0,%1,%2,%3}, [%4];"
        : "=r"(r[0]), "=r"(r[1]), "=r"(r[2]), "=r"(r[3]) : "r"(a));
}
__device__ __forceinline__ void ldm_x4t(uint32_t* r, uint32_t a) {
    asm volatile("ldmatrix.sync.aligned.m8n8.x4.trans.shared.b16 {%0,%1,%2,%3}, [%4];"
        : "=r"(r[0]), "=r"(r[1]), "=r"(r[2]), "=r"(r[3]) : "r"(a));
}
__device__ __forceinline__ uint32_t packh2(float a, float b) {
    __half2 h = __floats2half2_rn(a, b);
    return *(uint32_t*)&h;
}
#define CP_A16(dst, src) \
    asm volatile("cp.async.cg.shared.global [%0], [%1], 16;" :: "r"(dst), "l"(src) : "memory")
#define CP_COMMIT() asm volatile("cp.async.commit_group;" ::: "memory")
#define CP_WAIT(n)  asm volatile("cp.async.wait_group %0;" :: "n"(n) : "memory")

// ============ convert: fp32 inputs -> fp16 scratch ===========================
__global__ __launch_bounds__(256)
void conv_kernel(const float* __restrict__ X,
                 const float* __restrict__ Wq, const float* __restrict__ bq,
                 const float* __restrict__ Wk, const float* __restrict__ bk,
                 const float* __restrict__ Wv, const float* __restrict__ bv,
                 const float* __restrict__ Wo)
{
    int idx = blockIdx.x * 256 + threadIdx.x;
    if (idx < 1048576) {
        float4 v = ((const float4*)X)[idx];
        *(__half2*)&g_Xh[idx * 4]     = __floats2half2_rn(v.x, v.y);
        *(__half2*)&g_Xh[idx * 4 + 2] = __floats2half2_rn(v.z, v.w);
    } else if (idx < 1310720) {
        int i = idx - 1048576;
        float4 v = ((const float4*)Wo)[i];
        *(__half2*)&g_Woh[i * 4]     = __floats2half2_rn(v.x, v.y);
        *(__half2*)&g_Woh[i * 4 + 2] = __floats2half2_rn(v.z, v.w);
    } else if (idx < 1605632) {
        int u = idx - 1310720;
        int row = u / 288, c = (u % 288) * 4;
        float4 v;
        if (c < 1024)      v = *(const float4*)(Wq + row * 1024 + c);
        else if (c < 1088) v = *(const float4*)(Wk + row * 64 + c - 1024);
        else               v = *(const float4*)(Wv + row * 64 + c - 1088);
        __half* d = &g_Wqkv[row * NQKV + c];
        *(__half2*)d       = __floats2half2_rn(v.x, v.y);
        *(__half2*)(d + 2) = __floats2half2_rn(v.z, v.w);
    } else if (idx < 1605920) {
        int c = (idx - 1605632) * 4;
        float4 v;
        if (c < 1024)      v = *(const float4*)(bq + c);
        else if (c < 1088) v = *(const float4*)(bk + c - 1024);
        else               v = *(const float4*)(bv + c - 1088);
        *(float4*)&g_bqkv[c] = v;
    }
}

// ============ GEMM fp16: 128x128 tile, K-chunk 64, 3-stage cp.async ==========
// Inner loop: ALL 8 B-fragments of the chunk hoisted into registers up front,
// then a 4-ks mma sweep — LDSM latency hidden behind the mma tail.
#define GSTA 18432            // 128*72*2 (A part of a stage)
#define GSTW 17408            // 64*136*2 (W part of a stage)
#define GSTAGE 35840
#define GBI_B 107520          // 3*GSTAGE
#define G_SMEM 108032

__device__ __forceinline__ void g_issue(uint32_t sb, int buf, int k0, int tid,
                                        const __half* A, const __half* W,
                                        int WN, int m0, int n0)
{
    const uint32_t as = sb + buf * GSTAGE;
    const uint32_t ws = as + GSTA;
#pragma unroll
    for (int l = 0; l < 4; l++) {
        int idx = tid + l * 256;
        int r = idx >> 3, c8 = idx & 7;
        CP_A16(as + (uint32_t)(r * 72 + c8 * 8) * 2,
               (const void*)(A + (size_t)(m0 + r) * HIDDEN + k0 + c8 * 8));
    }
#pragma unroll
    for (int l = 0; l < 4; l++) {
        int idx = tid + l * 256;
        int r = idx >> 4, c8 = idx & 15;
        CP_A16(ws + (uint32_t)(r * 136 + c8 * 8) * 2,
               (const void*)(W + (size_t)(k0 + r) * WN + n0 + c8 * 8));
    }
}

__global__ __launch_bounds__(256, 2)
void gemm_h(const __half* __restrict__ A, const __half* __restrict__ W, int WN,
            const float* __restrict__ bias, float* __restrict__ C, int mode)
{
    extern __shared__ char smc[];
    const uint32_t sb = smem_u32(smc);
    float* Bias = (float*)(smc + GBI_B);

    const int tid = threadIdx.x, lane = tid & 31, wid = tid >> 5;
    const int g = lane >> 2, k4 = lane & 3;
    const int wr = wid >> 2, wc = wid & 3;
    const int m0 = blockIdx.y * 128;
    const int n0 = blockIdx.x * 128;

    if (tid < 128) Bias[tid] = bias[n0 + tid];

    g_issue(sb, 0, 0,  tid, A, W, WN, m0, n0); CP_COMMIT();
    g_issue(sb, 1, 64, tid, A, W, WN, m0, n0); CP_COMMIT();

    float acc[4][4][4] = {};
    int buf = 0;

    for (int kc = 0; kc < 16; ++kc) {
        if (kc < 15) CP_WAIT(1);
        else         CP_WAIT(0);
        __syncthreads();

        if (kc < 14) {
            int nb = buf + 2; if (nb >= 3) nb -= 3;
            g_issue(sb, nb, (kc + 2) * 64, tid, A, W, WN, m0, n0);
            CP_COMMIT();
        }

        const uint32_t as = sb + buf * GSTAGE;
        const uint32_t ws = as + GSTA;
        const int i = lane >> 3;

        // hoist all B fragments for this chunk (8 x ldm_x4t burst)
        uint32_t bfr[8][4];
#pragma unroll
        for (int ks = 0; ks < 4; ++ks)
#pragma unroll
            for (int p = 0; p < 2; p++)
                ldm_x4t(bfr[ks * 2 + p],
                        ws + (uint32_t)((ks * 16 + (i & 1) * 8 + (lane & 7)) * 136
                                        + wc * 32 + p * 16 + (i >> 1) * 8) * 2);

#pragma unroll
        for (int ks = 0; ks < 4; ++ks) {
            uint32_t a[4][4];
#pragma unroll
            for (int mt = 0; mt < 4; mt++)
                ldm_x4(a[mt], as + (uint32_t)((wr * 64 + mt * 16 + (lane & 15)) * 72
                                              + ks * 16 + (lane >> 4) * 8) * 2);
#pragma unroll
            for (int p = 0; p < 2; p++) {
                const uint32_t* b4 = bfr[ks * 2 + p];
#pragma unroll
                for (int mt = 0; mt < 4; mt++) {
                    mma16(acc[mt][2 * p],     a[mt], b4);
                    mma16(acc[mt][2 * p + 1], a[mt], b4 + 2);
                }
            }
        }
        if (++buf == 3) buf = 0;
    }

    // ---- epilogue: Q scaled by log2e/8 so softmax can use ex2 directly ----
    const float sc = (mode == 0 && n0 < 1024) ? 0.18033688f : 1.0f;
#pragma unroll
    for (int mt = 0; mt < 4; mt++) {
        const int r = m0 + wr * 64 + mt * 16 + g;
#pragma unroll
        for (int nt = 0; nt < 4; nt++) {
            const int c = wc * 32 + nt * 8 + 2 * k4;
            float v00 = (acc[mt][nt][0] + Bias[c])     * sc;
            float v01 = (acc[mt][nt][1] + Bias[c + 1]) * sc;
            float v10 = (acc[mt][nt][2] + Bias[c])     * sc;
            float v11 = (acc[mt][nt][3] + Bias[c + 1]) * sc;
            if (mode == 1) {
                float2 a0 = { v00, v01 }, a1 = { v10, v11 };
                *(float2*)(C + (size_t)r * HIDDEN + n0 + c) = a0;
                *(float2*)(C + (size_t)(r + 8) * HIDDEN + n0 + c) = a1;
            } else if (n0 < 1024) {
                *(__half2*)&g_Qh[(size_t)r * HIDDEN + n0 + c]       = __floats2half2_rn(v00, v01);
                *(__half2*)&g_Qh[(size_t)(r + 8) * HIDDEN + n0 + c] = __floats2half2_rn(v10, v11);
            } else if (c < 64) {
                *(__half2*)&g_Kh[(size_t)r * HDIM + c]       = __floats2half2_rn(v00, v01);
                *(__half2*)&g_Kh[(size_t)(r + 8) * HDIM + c] = __floats2half2_rn(v10, v11);
            } else {
                *(__half2*)&g_Vh[(size_t)r * HDIM + c - 64]       = __floats2half2_rn(v00, v01);
                *(__half2*)&g_Vh[(size_t)(r + 8) * HDIM + c - 64] = __floats2half2_rn(v10, v11);
            }
        }
    }
}

// ============ attention: 128 rows x 2 heads/CTA (R12/R14 optimum) ============
#define AQ_B  0               // 2 heads x 18432
#define AKV_B 36864           // K/V double buffer: buf*36864, V at +18432
#define AM_B  110592          // mask halves: 2 x 128 x 2B
#define ATT_SMEM 111104

__global__ __launch_bounds__(512, 1)
void attn_h(const int* __restrict__ mask)
{
    extern __shared__ char smc[];
    const uint32_t sb = smem_u32(smc);

    const int tid = threadIdx.x, lane = tid & 31, wid = tid >> 5;
    const int g = lane >> 2, k4 = lane & 3;
    const int ln = lane & 15;
    const int hsel = wid >> 3;          // 0..1: which head this warp serves
    const int wrow = wid & 7;           // row-tile within the head
    const int qt = blockIdx.x, hp = blockIdx.y, b = blockIdx.z;
    const int h = hp * 2 + hsel;

    const __half* Kb = g_Kh + (size_t)b * SEQ * HDIM;
    const __half* Vb = g_Vh + (size_t)b * SEQ * HDIM;
    const int*    Mb = mask + (size_t)b * SEQ;
    unsigned short* MskH = (unsigned short*)(smc + AM_B);

    // ---- prologue: Q tiles (both heads) + K/V tile 0 ----
#pragma unroll
    for (int l = 0; l < 4; l++) {
        int idx = tid + l * 512;            // 0..2047
        int hh = idx >> 10;                 // 0..1
        int r  = (idx >> 3) & 127;
        int c8 = idx & 7;
        const __half* src = g_Qh + ((size_t)(b * SEQ + qt * 128 + r)) * HIDDEN
                          + (hp * 2 + hh) * HDIM + c8 * 8;
        CP_A16(sb + AQ_B + hh * 18432 + (uint32_t)(r * 72 + c8 * 8) * 2, (const void*)src);
    }
    {
        const uint32_t kb = sb + AKV_B;
#pragma unroll
        for (int l = 0; l < 4; l++) {
            int idx = tid + l * 512;        // 0..2047
            int kv = idx >> 10;             // 0 = K, 1 = V
            int r  = (idx >> 3) & 127;
            int c8 = idx & 7;
            const __half* src = (kv ? Vb : Kb) + (size_t)r * HDIM + c8 * 8;
            CP_A16(kb + kv * 18432 + (uint32_t)(r * 72 + c8 * 8) * 2, (const void*)src);
        }
        if (tid < 128) MskH[tid] = Mb[tid] ? 0x3C00 : 0;
        CP_COMMIT();
    }
    CP_WAIT(0);
    __syncthreads();

    uint32_t qa[4][4];
#pragma unroll
    for (int ks = 0; ks < 4; ks++)
        ldm_x4(qa[ks], sb + AQ_B + hsel * 18432
                        + (uint32_t)((wrow * 16 + ln) * 72 + ks * 16 + (lane >> 4) * 8) * 2);

    float oacc[8][4] = {};
    float sum0 = 0.f, sum1 = 0.f;

    for (int kt = 0; kt < 16; ++kt) {
        if (kt > 0) {
            CP_WAIT(0);
            __syncthreads();
        }
        if (kt < 15) {
            const uint32_t kb = sb + AKV_B + ((kt + 1) & 1) * 36864;
            const size_t base = (size_t)((kt + 1) * 128) * HDIM;
#pragma unroll
            for (int l = 0; l < 4; l++) {
                int idx = tid + l * 512;
                int kv = idx >> 10;
                int r  = (idx >> 3) & 127;
                int c8 = idx & 7;
                const __half* src = (kv ? Vb : Kb) + base + (size_t)r * HDIM + c8 * 8;
                CP_A16(kb + kv * 18432 + (uint32_t)(r * 72 + c8 * 8) * 2, (const void*)src);
            }
            if (tid < 128) MskH[((kt + 1) & 1) * 128 + tid] = Mb[(kt + 1) * 128 + tid] ? 0x3C00 : 0;
            CP_COMMIT();
        }

        const uint32_t ksh = sb + AKV_B + (kt & 1) * 36864;
        const uint32_t vsh = ksh + 18432;
        const unsigned short* Mw = MskH + (kt & 1) * 128;

#pragma unroll
        for (int hf = 0; hf < 2; ++hf) {
            // ---- S' = (Q*log2e/8) @ K^T over 64 keys, fp32 accumulators ----
            float sacc[8][4] = {};
#pragma unroll
            for (int nt = 0; nt < 8; nt++) {
                const int krow = hf * 64 + nt * 8 + (lane & 7);
#pragma unroll
                for (int ks2 = 0; ks2 < 2; ks2++) {
                    uint32_t kb4[4];
                    ldm_x4(kb4, ksh + (uint32_t)(krow * 72 + ks2 * 32 + (lane >> 3) * 8) * 2);
                    mma16(sacc[nt], qa[2 * ks2],     kb4);
                    mma16(sacc[nt], qa[2 * ks2 + 1], kb4 + 2);
                }
            }
            // ---- P = 2^(S') via ex2.f16x2, masked; rowsum via add.f16x2 ----
            uint32_t ph0[8], ph1[8];
            uint32_t hs0 = 0, hs1 = 0;      // packed f16x2 partial row sums
#pragma unroll
            for (int nt = 0; nt < 8; nt++) {
                const int c = hf * 64 + nt * 8 + 2 * k4;
                uint32_t e01 = packh2(sacc[nt][0], sacc[nt][1]);
                uint32_t e23 = packh2(sacc[nt][2], sacc[nt][3]);
                asm("ex2.approx.f16x2 %0, %1;" : "=r"(e01) : "r"(e01));
                asm("ex2.approx.f16x2 %0, %1;" : "=r"(e23) : "r"(e23));
                const uint32_t mh = *(const uint32_t*)&Mw[c];
                asm("mul.rn.f16x2 %0, %1, %2;" : "=r"(ph0[nt]) : "r"(e01), "r"(mh));
                asm("mul.rn.f16x2 %0, %1, %2;" : "=r"(ph1[nt]) : "r"(e23), "r"(mh));
                asm("add.rn.f16x2 %0, %0, %1;" : "+r"(hs0) : "r"(ph0[nt]));
                asm("add.rn.f16x2 %0, %0, %1;" : "+r"(hs1) : "r"(ph1[nt]));
            }
            // promote 64-key partial sums to fp32
            {
                __half2 h0 = *(__half2*)&hs0, h1 = *(__half2*)&hs1;
                float2 f0 = __half22float2(h0), f1 = __half22float2(h1);
                sum0 += f0.x + f0.y;
                sum1 += f1.x + f1.y;
            }
            // ---- O += P @ V (fp32 acc) ----
#pragma unroll
            for (int j = 0; j < 4; j++) {
                uint32_t a[4] = { ph0[2 * j], ph1[2 * j], ph0[2 * j + 1], ph1[2 * j + 1] };
                const int vrow = hf * 64 + j * 16 + ln;
#pragma unroll
                for (int d2 = 0; d2 < 4; d2++) {
                    uint32_t vb4[4];
                    ldm_x4t(vb4, vsh + (uint32_t)(vrow * 72 + d2 * 16 + (lane >> 4) * 8) * 2);
                    mma16(oacc[2 * d2],     a, vb4);
                    mma16(oacc[2 * d2 + 1], a, vb4 + 2);
                }
            }
        }
    }

    // ---- quad reduction across k4 lanes ----
    sum0 += __shfl_xor_sync(0xffffffffu, sum0, 1);
    sum0 += __shfl_xor_sync(0xffffffffu, sum0, 2);
    sum1 += __shfl_xor_sync(0xffffffffu, sum1, 1);
    sum1 += __shfl_xor_sync(0xffffffffu, sum1, 2);
    const float inv0 = 1.f / sum0;
    const float inv1 = 1.f / sum1;

    __half* Ob = g_Ah + ((size_t)(b * SEQ + qt * 128 + wrow * 16 + g)) * HIDDEN + h * HDIM;
#pragma unroll
    for (int d = 0; d < 8; d++) {
        int c = d * 8 + 2 * k4;
        *(__half2*)(Ob + c) = __floats2half2_rn(oacc[d][0] * inv0, oacc[d][1] * inv0);
        *(__half2*)(Ob + (size_t)8 * HIDDEN + c) = __floats2half2_rn(oacc[d][2] * inv1,
                                                                     oacc[d][3] * inv1);
    }
}

// ---------------- launch --------------------------------------------------
extern "C" void kernel_launch(void* const* d_in, const int* in_sizes, int n_in,
                              void* d_out, int out_size)
{
    const float* X    = (const float*)d_in[0];
    const float* Wq   = (const float*)d_in[1];
    const float* bq   = (const float*)d_in[2];
    const float* Wk   = (const float*)d_in[3];
    const float* bk   = (const float*)d_in[4];
    const float* Wv   = (const float*)d_in[5];
    const float* bv   = (const float*)d_in[6];
    const float* Wo   = (const float*)d_in[7];
    const float* bo   = (const float*)d_in[8];
    const int*   mask = (const int*)d_in[9];
    float* out = (float*)d_out;

    __half *xh, *ah, *wqkv, *woh;
    float* bqkv;
    cudaGetSymbolAddress((void**)&xh,   g_Xh);
    cudaGetSymbolAddress((void**)&ah,   g_Ah);
    cudaGetSymbolAddress((void**)&wqkv, g_Wqkv);
    cudaGetSymbolAddress((void**)&woh,  g_Woh);
    cudaGetSymbolAddress((void**)&bqkv, g_bqkv);

    cudaFuncSetAttribute(gemm_h, cudaFuncAttributeMaxDynamicSharedMemorySize, G_SMEM);
    cudaFuncSetAttribute(attn_h, cudaFuncAttributeMaxDynamicSharedMemorySize, ATT_SMEM);

    // 0) convert inputs to fp16 scratch
    conv_kernel<<<6274, 256>>>(X, Wq, bq, Wk, bk, Wv, bv, Wo);

    // 1) fused QKV projection
    dim3 g1(NQKV / 128, MTOT / 128);
    gemm_h<<<g1, 256, G_SMEM>>>(xh, wqkv, NQKV, bqkv, nullptr, 0);

    // 2) attention: 128 rows x 2 heads per CTA (shared K/V)
    dim3 g2(SEQ / 128, NHEADS / 2, BATCH);
    attn_h<<<g2, 512, ATT_SMEM>>>(mask);

    // 3) O projection -> d_out (f32 + bias)
    dim3 g3(HIDDEN / 128, MTOT / 128);
    gemm_h<<<g3, 256, G_SMEM>>>(ah, woh, HIDDEN, bo, out, 1);
}